// round 8
// baseline (speedup 1.0000x reference)
#include <cuda_runtime.h>
#include <cuda_bf16.h>
#include <mma.h>
#include <math.h>
#include <stdint.h>

using namespace nvcuda;

#define NP     1024
#define EMBD   64
#define HID    128
#define NCELL  64
#define PN     4096     // NCELL * EMBD
#define KX     256      // [emb(64) | pool(64) | h0(128)]
#define MIX    20
#define NOUT   120
#define NBLK   128      // persistent grid size; 1 CTA/SM, all resident (<=148 SMs)

// ---------------- device scratch (static, no allocations) ----------------
__device__ float g_P[NP * PN];        // 16 MB
__device__ float g_X[NP * KX];        // 1 MB
__device__ float g_h[NP * HID];       // 0.5 MB
__device__ unsigned g_cnt[4];         // barrier arrive counters (self-resetting)
__device__ unsigned g_done[4];        // barrier exit counters

__device__ __forceinline__ float sigm(float x) { return 1.0f / (1.0f + expf(-x)); }

// split one float4 into hi/lo bf16x2 pairs and store to smem
__device__ __forceinline__ void split_store(__nv_bfloat16* d1, __nv_bfloat16* d2, float4 v) {
    __nv_bfloat162 h1a, h1b, h2a, h2b;
    h1a.x = __float2bfloat16(v.x); h2a.x = __float2bfloat16(v.x - __bfloat162float(h1a.x));
    h1a.y = __float2bfloat16(v.y); h2a.y = __float2bfloat16(v.y - __bfloat162float(h1a.y));
    h1b.x = __float2bfloat16(v.z); h2b.x = __float2bfloat16(v.z - __bfloat162float(h1b.x));
    h1b.y = __float2bfloat16(v.w); h2b.y = __float2bfloat16(v.w - __bfloat162float(h1b.y));
    *(__nv_bfloat162*)(d1)     = h1a;
    *(__nv_bfloat162*)(d1 + 2) = h1b;
    *(__nv_bfloat162*)(d2)     = h2a;
    *(__nv_bfloat162*)(d2 + 2) = h2b;
}

// Self-resetting grid barrier. Safe: all NBLK CTAs are co-resident (1 CTA/SM,
// NBLK=128 <= 148 SMs at this smem/reg footprint). Counters return to 0 every
// launch, so graph replays see clean state.
__device__ __forceinline__ void grid_barrier(int b) {
    __syncthreads();
    if (threadIdx.x == 0) {
        __threadfence();                       // release prior writes
        atomicAdd(&g_cnt[b], 1u);
        while (*((volatile unsigned*)&g_cnt[b]) < (unsigned)NBLK) { }
        __threadfence();                       // acquire
        const unsigned d = atomicAdd(&g_done[b], 1u);
        if (d == (unsigned)(NBLK - 1)) {       // last one out resets
            g_done[b] = 0u;
            __threadfence();
            *((volatile unsigned*)&g_cnt[b]) = 0u;
        }
    }
    __syncthreads();
}

// ---------------- smem layout constants ----------------
#define LDP   136
#define TILEP (128 * LDP)
#define LDG2  264
#define TILEG (64 * LDG2)
#define LDO   136
// max over phases: gates = 4*TILEG*2 + 64*68*4 = 152576 (P phase = 139264)
#define SMEM_BYTES 152576

struct ScatterSmem {
    float sx[NP];
    float sy[NP];
    int   slist[NP];
    int   wcnt[8];
    float sred[4][64];
};

__global__ __launch_bounds__(256, 1) void fused_kernel(
        const float* __restrict__ xabs, const float* __restrict__ h0,
        const float* __restrict__ c0,
        const float* __restrict__ W_emb, const float* __restrict__ b_emb,
        const float* __restrict__ Wsoc,  const float* __restrict__ b_soc,
        const float* __restrict__ W_ih,  const float* __restrict__ W_hh,
        const float* __restrict__ b_ih,  const float* __restrict__ b_hh,
        const float* __restrict__ W_out, const float* __restrict__ b_out,
        float* __restrict__ out) {
    extern __shared__ __align__(16) char smem_raw[];
    const int t    = threadIdx.x;
    const int wid  = t >> 5;
    const int lane = t & 31;
    const int bid  = blockIdx.x;

    // ================= Phase 1: P-GEMM (2 tiles of 128x128 per CTA) =================
    {
        __nv_bfloat16* sA1 = (__nv_bfloat16*)smem_raw;
        __nv_bfloat16* sA2 = sA1 + TILEP;
        __nv_bfloat16* sB1 = sA1 + 2 * TILEP;
        __nv_bfloat16* sB2 = sA1 + 3 * TILEP;
        const int warp_m = wid & 1;
        const int warp_n = wid >> 1;

        for (int tile = bid; tile < 256; tile += NBLK) {
            const int row0 = (tile & 7) * 128;
            const int col0 = (tile >> 3) * 128;
            __syncthreads();   // smem reuse across tile iterations
            #pragma unroll
            for (int i = t; i < 4096; i += 256) {
                const int row = i >> 5, k4 = i & 31;
                const float4 v = *(const float4*)&h0[(row0 + row) * HID + k4 * 4];
                split_store(sA1 + row * LDP + k4 * 4, sA2 + row * LDP + k4 * 4, v);
            }
            #pragma unroll
            for (int i = t; i < 4096; i += 256) {
                const int row = i >> 5, k4 = i & 31;
                const int ce = col0 + row;
                const int e = ce & 63, c = ce >> 6;
                const float4 v = *(const float4*)&Wsoc[e * (NCELL * HID) + c * HID + k4 * 4];
                split_store(sB1 + row * LDP + k4 * 4, sB2 + row * LDP + k4 * 4, v);
            }
            __syncthreads();

            wmma::fragment<wmma::accumulator, 16, 16, 16, float> acc[4][2];
            #pragma unroll
            for (int i = 0; i < 4; i++)
                #pragma unroll
                for (int j = 0; j < 2; j++)
                    wmma::fill_fragment(acc[i][j], 0.0f);

            wmma::fragment<wmma::matrix_a, 16, 16, 16, __nv_bfloat16, wmma::row_major> af;
            wmma::fragment<wmma::matrix_b, 16, 16, 16, __nv_bfloat16, wmma::col_major> bf[2];

            #pragma unroll
            for (int term = 0; term < 3; term++) {
                const __nv_bfloat16* sA = (term == 1) ? sA2 : sA1;
                const __nv_bfloat16* sB = (term == 2) ? sB2 : sB1;
                #pragma unroll
                for (int k0 = 0; k0 < 8; k0++) {
                    #pragma unroll
                    for (int j = 0; j < 2; j++)
                        wmma::load_matrix_sync(bf[j], sB + (warp_n * 32 + j * 16) * LDP + k0 * 16, LDP);
                    #pragma unroll
                    for (int i = 0; i < 4; i++) {
                        wmma::load_matrix_sync(af, sA + (warp_m * 64 + i * 16) * LDP + k0 * 16, LDP);
                        wmma::mma_sync(acc[i][0], af, bf[0], acc[i][0]);
                        wmma::mma_sync(acc[i][1], af, bf[1], acc[i][1]);
                    }
                }
            }

            #pragma unroll
            for (int i = 0; i < 4; i++)
                #pragma unroll
                for (int j = 0; j < 2; j++) {
                    float* dst = g_P + (size_t)(row0 + warp_m * 64 + i * 16) * PN
                                     + col0 + warp_n * 32 + j * 16;
                    wmma::store_matrix_sync(dst, acc[i][j], PN, wmma::mem_row_major);
                }
        }
    }
    grid_barrier(0);

    // ================= Phase 2: pair gather + X assembly (8 n's per CTA) =================
    {
        ScatterSmem* S = (ScatterSmem*)smem_raw;
        for (int i = t; i < NP; i += 256) {
            const float2 v = ((const float2*)xabs)[i];
            S->sx[i] = v.x;
            S->sy[i] = v.y;
        }
        __syncthreads();

        for (int nn = 0; nn < 8; nn++) {
            const int n = bid * 8 + nn;
            const float wl = S->sx[n] - 0.2f;
            const float bl = S->sy[n] - 0.2f;

            // classification: 8 warps x 128 m's (4 ballots each)
            int cells[4];
            unsigned masks[4];
            int cnt = 0;
            #pragma unroll
            for (int j = 0; j < 4; j++) {
                const int m = wid * 128 + j * 32 + lane;
                const float dx = S->sx[m] - wl;
                const float dy = S->sy[m] - bl;
                int cell = -1;
                if (dx >= 0.0f && dx < 0.4f && dy >= 0.0f && dy < 0.4f && m != n) {
                    const int cx = (int)floorf(__fmul_rn(__fdiv_rn(dx, 0.4f), 8.0f));
                    const int cy = (int)floorf(__fmul_rn(__fdiv_rn(dy, 0.4f), 8.0f));
                    if (cx >= 0 && cx < 8 && cy >= 0 && cy < 8) cell = cx + cy * 8;
                }
                cells[j] = (cell >= 0) ? (m * PN + cell * EMBD) : -1;
                masks[j] = __ballot_sync(0xFFFFFFFFu, cell >= 0);
                cnt += __popc(masks[j]);
            }
            if (lane == 0) S->wcnt[wid] = cnt;

            // independent work for this n
            if (t < 128) {
                g_X[n * KX + 128 + t] = h0[n * HID + t];
            } else if (t < 192) {
                const int e2 = t - 128;
                const float e = S->sx[n] * W_emb[2 * e2] + S->sy[n] * W_emb[2 * e2 + 1] + b_emb[e2];
                g_X[n * KX + e2] = fmaxf(e, 0.0f);
            }
            __syncthreads();

            int base = 0, tot = 0;
            #pragma unroll
            for (int ww = 0; ww < 8; ww++) {
                if (ww < wid) base += S->wcnt[ww];
                tot += S->wcnt[ww];
            }
            #pragma unroll
            for (int j = 0; j < 4; j++) {
                if (cells[j] >= 0)
                    S->slist[base + __popc(masks[j] & ((1u << lane) - 1u))] = cells[j];
                base += __popc(masks[j]);
            }
            __syncthreads();

            // gather: 4 slots x 64 e, unroll 8 for MLP
            const int slot = t >> 6;
            const int e    = t & 63;
            float acc = 0.0f;
            int i = slot;
            for (; i + 32 <= tot; i += 32) {
                acc += g_P[(size_t)S->slist[i]      + e];
                acc += g_P[(size_t)S->slist[i + 4]  + e];
                acc += g_P[(size_t)S->slist[i + 8]  + e];
                acc += g_P[(size_t)S->slist[i + 12] + e];
                acc += g_P[(size_t)S->slist[i + 16] + e];
                acc += g_P[(size_t)S->slist[i + 20] + e];
                acc += g_P[(size_t)S->slist[i + 24] + e];
                acc += g_P[(size_t)S->slist[i + 28] + e];
            }
            for (; i < tot; i += 4) acc += g_P[(size_t)S->slist[i] + e];
            S->sred[slot][e] = acc;
            __syncthreads();

            if (t < 64) {
                const float s = S->sred[0][e] + S->sred[1][e] + S->sred[2][e] + S->sred[3][e] + b_soc[e];
                g_X[n * KX + 64 + e] = fmaxf(s, 0.0f);
            }
            __syncthreads();   // before next n reuses wcnt/slist/sred
        }
    }
    grid_barrier(1);

    // ================= Phase 3: gates GEMM + LSTM (1 tile per CTA) =================
    {
        __nv_bfloat16* sA1 = (__nv_bfloat16*)smem_raw;
        __nv_bfloat16* sA2 = sA1 + TILEG;
        __nv_bfloat16* sB1 = sA1 + 2 * TILEG;
        __nv_bfloat16* sB2 = sA1 + 3 * TILEG;
        float* sg = (float*)(sA1 + 4 * TILEG);   // [64][68]

        const int row0 = (bid >> 3) * 64;
        const int d0   = (bid & 7) * 16;
        const int warp_m = wid & 3;
        const int warp_n = wid >> 2;

        #pragma unroll
        for (int i = t; i < 4096; i += 256) {
            const int row = i >> 6, k4 = i & 63;
            const float4 v = *(const float4*)&g_X[(row0 + row) * KX + k4 * 4];
            split_store(sA1 + row * LDG2 + k4 * 4, sA2 + row * LDG2 + k4 * 4, v);
        }
        #pragma unroll
        for (int i = t; i < 4096; i += 256) {
            const int cc = i >> 6, k4 = i & 63;
            const int wrow = (cc >> 4) * 128 + d0 + (cc & 15);
            const float4 v = (k4 < 32) ? *(const float4*)&W_ih[wrow * 128 + k4 * 4]
                                       : *(const float4*)&W_hh[wrow * 128 + (k4 - 32) * 4];
            split_store(sB1 + cc * LDG2 + k4 * 4, sB2 + cc * LDG2 + k4 * 4, v);
        }
        __syncthreads();

        wmma::fragment<wmma::accumulator, 16, 16, 16, float> acc[2];
        wmma::fill_fragment(acc[0], 0.0f);
        wmma::fill_fragment(acc[1], 0.0f);
        wmma::fragment<wmma::matrix_a, 16, 16, 16, __nv_bfloat16, wmma::row_major> af;
        wmma::fragment<wmma::matrix_b, 16, 16, 16, __nv_bfloat16, wmma::col_major> bf[2];

        #pragma unroll
        for (int term = 0; term < 3; term++) {
            const __nv_bfloat16* sA = (term == 1) ? sA2 : sA1;
            const __nv_bfloat16* sB = (term == 2) ? sB2 : sB1;
            #pragma unroll
            for (int k0 = 0; k0 < 16; k0++) {
                wmma::load_matrix_sync(af, sA + (warp_m * 16) * LDG2 + k0 * 16, LDG2);
                #pragma unroll
                for (int j = 0; j < 2; j++) {
                    wmma::load_matrix_sync(bf[j], sB + (warp_n * 32 + j * 16) * LDG2 + k0 * 16, LDG2);
                    wmma::mma_sync(acc[j], af, bf[j], acc[j]);
                }
            }
        }

        #pragma unroll
        for (int j = 0; j < 2; j++)
            wmma::store_matrix_sync(sg + (warp_m * 16) * 68 + warp_n * 32 + j * 16,
                                    acc[j], 68, wmma::mem_row_major);
        __syncthreads();

        #pragma unroll
        for (int idx = t; idx < 1024; idx += 256) {
            const int rl = idx >> 4;
            const int dd = idx & 15;
            const int d = d0 + dd;
            const float ig = sg[rl * 68 + dd]      + b_ih[d]       + b_hh[d];
            const float fg = sg[rl * 68 + 16 + dd] + b_ih[128 + d] + b_hh[128 + d];
            const float gg = sg[rl * 68 + 32 + dd] + b_ih[256 + d] + b_hh[256 + d];
            const float og = sg[rl * 68 + 48 + dd] + b_ih[384 + d] + b_hh[384 + d];
            const int n = row0 + rl;
            const float c = sigm(fg) * c0[n * HID + d] + sigm(ig) * tanhf(gg);
            g_h[n * HID + d] = sigm(og) * tanhf(c);
        }
    }
    grid_barrier(2);

    // ================= Phase 4: output projection (16 rows x 64 cols per CTA) =================
    {
        __nv_bfloat16* sA1 = (__nv_bfloat16*)smem_raw;            // 16 x LDO
        __nv_bfloat16* sA2 = sA1 + 16 * LDO;
        __nv_bfloat16* sB1 = sA1 + 2 * 16 * LDO;                  // 64 x LDO
        __nv_bfloat16* sB2 = sB1 + 64 * LDO;
        float* so = (float*)(sB2 + 64 * LDO);                     // [16][68]

        const int row0 = (bid >> 1) * 16;
        const int col0 = (bid & 1) * 64;

        #pragma unroll
        for (int i = t; i < 512; i += 256) {
            const int row = i >> 5, k4 = i & 31;
            const float4 v = *(const float4*)&g_h[(row0 + row) * HID + k4 * 4];
            split_store(sA1 + row * LDO + k4 * 4, sA2 + row * LDO + k4 * 4, v);
        }
        #pragma unroll
        for (int i = t; i < 2048; i += 256) {
            const int ee = i >> 5, k4 = i & 31;
            const int eg = col0 + ee;
            const float4 v = (eg < NOUT) ? *(const float4*)&W_out[eg * HID + k4 * 4]
                                         : make_float4(0.f, 0.f, 0.f, 0.f);
            split_store(sB1 + ee * LDO + k4 * 4, sB2 + ee * LDO + k4 * 4, v);
        }
        __syncthreads();

        if (wid < 4) {
            wmma::fragment<wmma::accumulator, 16, 16, 16, float> acc;
            wmma::fill_fragment(acc, 0.0f);
            wmma::fragment<wmma::matrix_a, 16, 16, 16, __nv_bfloat16, wmma::row_major> af;
            wmma::fragment<wmma::matrix_b, 16, 16, 16, __nv_bfloat16, wmma::col_major> bf;
            #pragma unroll
            for (int term = 0; term < 3; term++) {
                const __nv_bfloat16* sA = (term == 1) ? sA2 : sA1;
                const __nv_bfloat16* sB = (term == 2) ? sB2 : sB1;
                #pragma unroll
                for (int k0 = 0; k0 < 8; k0++) {
                    wmma::load_matrix_sync(af, sA + k0 * 16, LDO);
                    wmma::load_matrix_sync(bf, sB + (wid * 16) * LDO + k0 * 16, LDO);
                    wmma::mma_sync(acc, af, bf, acc);
                }
            }
            wmma::store_matrix_sync(so + wid * 16, acc, 68, wmma::mem_row_major);
        }
        __syncthreads();

        #pragma unroll
        for (int idx = t; idx < 16 * 64; idx += 256) {
            const int r  = idx >> 6;
            const int cc = idx & 63;
            const int e  = col0 + cc;
            if (e < NOUT) {
                const float v = so[r * 68 + cc] + b_out[e];
                out[(e / MIX) * (NP * MIX) + (row0 + r) * MIX + (e % MIX)] = v;
            }
        }
    }
}

// ---------------- launch ----------------
extern "C" void kernel_launch(void* const* d_in, const int* in_sizes, int n_in,
                              void* d_out, int out_size) {
    const float* xabs  = (const float*)d_in[0];
    const float* h0    = (const float*)d_in[1];
    const float* c0    = (const float*)d_in[2];
    const float* W_emb = (const float*)d_in[3];
    const float* b_emb = (const float*)d_in[4];
    const float* W_soc = (const float*)d_in[5];
    const float* b_soc = (const float*)d_in[6];
    const float* W_ih  = (const float*)d_in[7];
    const float* W_hh  = (const float*)d_in[8];
    const float* b_ih  = (const float*)d_in[9];
    const float* b_hh  = (const float*)d_in[10];
    const float* W_out = (const float*)d_in[11];
    const float* b_out = (const float*)d_in[12];
    float* out = (float*)d_out;

    cudaFuncSetAttribute(fused_kernel, cudaFuncAttributeMaxDynamicSharedMemorySize, SMEM_BYTES);

    fused_kernel<<<NBLK, 256, SMEM_BYTES>>>(xabs, h0, c0, W_emb, b_emb, W_soc, b_soc,
                                            W_ih, W_hh, b_ih, b_hh, W_out, b_out, out);
}